// round 1
// baseline (speedup 1.0000x reference)
#include <cuda_runtime.h>

// Shapes (fixed by the problem):
//   x  : (32, 3, 640, 640) fp32
//   W1 : (192, 64), b1 : (64), W2 : (64, 15)
#define B    32
#define C    3
#define H    640
#define W    640
#define HW   (H * W)        // 409600 floats per channel
#define HW4  (HW / 4)       // 102400 float4 per channel
#define POOL 8
#define HID  64
#define NP   15             // 9 (M) + 3 (bias) + 3 (gamma)

// Scratch (allocation-free rule: __device__ globals)
__device__ float g_pooled[B * C * POOL * POOL];   // (b, c*64 + pr*8 + pc)
__device__ float g_params[B * NP];                // per-sample sigmoid outputs

// ---------------------------------------------------------------------------
// Kernel 1: adaptive avg pool 8x8.
// Grid: B*C*POOL blocks, one per (b, c, pool-row). 256 threads = 8 warps.
// Warp w owns pool-column w: its 32 lanes sum the 80x80 block (20 float4 wide,
// 80 rows). Single static register accumulator per thread -> no local spills.
// Deterministic shfl tree reduction (no float atomics).
// ---------------------------------------------------------------------------
__global__ __launch_bounds__(256) void pool_kernel(const float* __restrict__ x) {
    int id = blockIdx.x;          // b*24 + c*8 + pr
    int pr = id & 7;
    int bc = id >> 3;             // b*3 + c

    int lane = threadIdx.x & 31;
    int pc   = threadIdx.x >> 5;  // warp id == pool column

    const float4* base = reinterpret_cast<const float4*>(x)
                       + (size_t)bc * HW4 + (size_t)pr * (80 * 160) + pc * 20;

    float acc = 0.0f;
    // 80 rows x 20 float4 per pool cell = 1600 float4, strided by 32 lanes.
    #pragma unroll 5
    for (int j = lane; j < 1600; j += 32) {
        int row = j / 20;
        int f   = j % 20;
        float4 v = base[(size_t)row * 160 + f];
        acc += (v.x + v.y) + (v.z + v.w);
    }
    // warp tree reduction
    acc += __shfl_down_sync(0xffffffffu, acc, 16);
    acc += __shfl_down_sync(0xffffffffu, acc, 8);
    acc += __shfl_down_sync(0xffffffffu, acc, 4);
    acc += __shfl_down_sync(0xffffffffu, acc, 2);
    acc += __shfl_down_sync(0xffffffffu, acc, 1);

    if (lane == 0) {
        g_pooled[bc * 64 + pr * 8 + pc] = acc * (1.0f / 6400.0f);
    }
}

// ---------------------------------------------------------------------------
// Kernel 2: tiny MLP. One block per sample, 64 threads (one per hidden unit).
//   hid = clip(feat @ W1 + b1, 0, 6);  params = sigmoid(hid @ W2)
// ---------------------------------------------------------------------------
__global__ __launch_bounds__(64) void mlp_kernel(const float* __restrict__ W1,
                                                 const float* __restrict__ b1,
                                                 const float* __restrict__ W2) {
    int b = blockIdx.x;
    __shared__ float feat[C * POOL * POOL];  // 192
    __shared__ float hid[HID];

    for (int i = threadIdx.x; i < 192; i += 64)
        feat[i] = g_pooled[b * 192 + i];
    __syncthreads();

    int h = threadIdx.x;
    float s = b1[h];
    #pragma unroll 8
    for (int j = 0; j < 192; j++)
        s = fmaf(feat[j], W1[j * HID + h], s);
    hid[h] = fminf(fmaxf(s, 0.0f), 6.0f);
    __syncthreads();

    if (h < NP) {
        float s2 = 0.0f;
        #pragma unroll 8
        for (int j = 0; j < HID; j++)
            s2 = fmaf(hid[j], W2[j * NP + h], s2);
        g_params[b * NP + h] = 1.0f / (1.0f + __expf(-s2));
    }
}

// ---------------------------------------------------------------------------
// Kernel 3: per-pixel 3x3 color transform + pow(gamma) + normalize.
// Grid: (HW4/256, B). Thread handles 4 pixels (float4) across all 3 channels:
// 48 B in, 48 B out. Normalization folded: r*inv_std - mean*inv_std.
// ---------------------------------------------------------------------------
__global__ __launch_bounds__(256) void transform_kernel(const float* __restrict__ x,
                                                        float* __restrict__ out) {
    int b = blockIdx.y;
    __shared__ float sp[NP];
    if (threadIdx.x < NP) sp[threadIdx.x] = g_params[b * NP + threadIdx.x];
    __syncthreads();

    int idx = blockIdx.x * 256 + threadIdx.x;   // [0, HW4) exactly
    const float4* xb = reinterpret_cast<const float4*>(x)   + (size_t)b * 3 * HW4 + idx;
    float4*       ob = reinterpret_cast<float4*>(out)       + (size_t)b * 3 * HW4 + idx;

    float4 v0 = xb[0];
    float4 v1 = xb[HW4];
    float4 v2 = xb[2 * HW4];

    const float mean_[3] = {0.485f, 0.456f, 0.406f};
    const float istd_[3] = {1.0f / 0.229f, 1.0f / 0.224f, 1.0f / 0.225f};

    #pragma unroll
    for (int i = 0; i < 3; i++) {
        float m0 = sp[i * 3 + 0], m1 = sp[i * 3 + 1], m2 = sp[i * 3 + 2];
        float bi = sp[9 + i];
        float g  = sp[12 + i];
        float is = istd_[i];
        float mo = mean_[i] * is;

        float4 r;
        r.x = __powf(fmaf(m0, v0.x, fmaf(m1, v1.x, fmaf(m2, v2.x, bi))), g) * is - mo;
        r.y = __powf(fmaf(m0, v0.y, fmaf(m1, v1.y, fmaf(m2, v2.y, bi))), g) * is - mo;
        r.z = __powf(fmaf(m0, v0.z, fmaf(m1, v1.z, fmaf(m2, v2.z, bi))), g) * is - mo;
        r.w = __powf(fmaf(m0, v0.w, fmaf(m1, v1.w, fmaf(m2, v2.w, bi))), g) * is - mo;
        ob[(size_t)i * HW4] = r;
    }
}

// ---------------------------------------------------------------------------
extern "C" void kernel_launch(void* const* d_in, const int* in_sizes, int n_in,
                              void* d_out, int out_size) {
    const float* x  = (const float*)d_in[0];
    const float* W1 = (const float*)d_in[1];
    const float* b1 = (const float*)d_in[2];
    const float* W2 = (const float*)d_in[3];
    float* out = (float*)d_out;

    pool_kernel<<<B * C * POOL, 256>>>(x);
    mlp_kernel<<<B, HID>>>(W1, b1, W2);
    transform_kernel<<<dim3(HW4 / 256, B), 256>>>(x, out);
}

// round 2
// speedup vs baseline: 1.0007x; 1.0007x over previous
#include <cuda_runtime.h>

// Shapes (fixed by the problem):
//   x  : (32, 3, 640, 640) fp32
//   W1 : (192, 64), b1 : (64), W2 : (64, 15)
#define B    32
#define C    3
#define H    640
#define W    640
#define HW   (H * W)        // 409600 floats per channel
#define HW4  (HW / 4)       // 102400 float4 per channel
#define POOL 8
#define HID  64
#define NP   15             // 9 (M) + 3 (bias) + 3 (gamma)

// Scratch (allocation-free rule: __device__ globals)
__device__ float g_pooled[B * C * POOL * POOL];   // (b, c*64 + pr*8 + pc)
__device__ float g_params[B * NP];                // per-sample sigmoid outputs

// ---------------------------------------------------------------------------
// Kernel 1: adaptive avg pool 8x8.
// Grid: B*C*POOL = 768 blocks, one per (b, c, pool-row). 320 threads.
// Thread owns float4-column f = tid%160, row-parity r0 = tid/160; streams 40
// rows with a FIXED stride (no div/mod in the loop) so ptxas batches loads
// (high MLP_p1). Shared-memory reduction, fixed order -> deterministic.
// ---------------------------------------------------------------------------
__global__ __launch_bounds__(320) void pool_kernel(const float* __restrict__ x) {
    int id = blockIdx.x;          // b*24 + c*8 + pr
    int pr = id & 7;
    int bc = id >> 3;             // b*3 + c

    int tid = threadIdx.x;
    int f   = tid % 160;          // float4 column within the row (640/4)
    int r0  = tid / 160;          // 0 or 1

    const float4* base = reinterpret_cast<const float4*>(x)
                       + (size_t)bc * HW4 + (size_t)pr * (80 * 160) + f
                       + (size_t)r0 * 160;

    float acc = 0.0f;
    #pragma unroll
    for (int r = 0; r < 40; r++) {                 // rows r0, r0+2, ..., 78/79
        float4 v = base[(size_t)r * 320];          // stride = 2 rows
        acc += (v.x + v.y) + (v.z + v.w);
    }

    __shared__ float s[320];
    s[tid] = acc;
    __syncthreads();

    if (tid < 8) {                                 // tid == pool column pc
        float t = 0.0f;
        #pragma unroll
        for (int k = 0; k < 20; k++)
            t += s[tid * 20 + k] + s[160 + tid * 20 + k];
        g_pooled[bc * 64 + pr * 8 + tid] = t * (1.0f / 6400.0f);
    }
}

// ---------------------------------------------------------------------------
// Kernel 2: tiny MLP. One block per sample, 64 threads (one per hidden unit).
//   hid = clip(feat @ W1 + b1, 0, 6);  params = sigmoid(hid @ W2)
// ---------------------------------------------------------------------------
__global__ __launch_bounds__(64) void mlp_kernel(const float* __restrict__ W1,
                                                 const float* __restrict__ b1,
                                                 const float* __restrict__ W2) {
    int b = blockIdx.x;
    __shared__ float feat[C * POOL * POOL];  // 192
    __shared__ float hid[HID];

    for (int i = threadIdx.x; i < 192; i += 64)
        feat[i] = g_pooled[b * 192 + i];
    __syncthreads();

    int h = threadIdx.x;
    float s = b1[h];
    #pragma unroll 8
    for (int j = 0; j < 192; j++)
        s = fmaf(feat[j], W1[j * HID + h], s);
    hid[h] = fminf(fmaxf(s, 0.0f), 6.0f);
    __syncthreads();

    if (h < NP) {
        float s2 = 0.0f;
        #pragma unroll 8
        for (int j = 0; j < HID; j++)
            s2 = fmaf(hid[j], W2[j * NP + h], s2);
        g_params[b * NP + h] = 1.0f / (1.0f + __expf(-s2));
    }
}

// ---------------------------------------------------------------------------
// Kernel 3: per-pixel 3x3 color transform + pow(gamma) + normalize.
// Each thread handles TWO float4 per channel (6 loads in flight before any
// compute -> MLP=6). Streaming stores (__stcs) keep the output write stream
// evict-first in L2 so pool's x lines survive for transform's re-read.
// Grid: (HW4/512, B), 256 threads.
// ---------------------------------------------------------------------------
__global__ __launch_bounds__(256) void transform_kernel(const float* __restrict__ x,
                                                        float* __restrict__ out) {
    int b = blockIdx.y;
    __shared__ float sp[NP];
    if (threadIdx.x < NP) sp[threadIdx.x] = g_params[b * NP + threadIdx.x];
    __syncthreads();

    int idx = blockIdx.x * 512 + threadIdx.x;   // first float4; second at +256
    const float4* xb = reinterpret_cast<const float4*>(x)   + (size_t)b * 3 * HW4 + idx;
    float4*       ob = reinterpret_cast<float4*>(out)       + (size_t)b * 3 * HW4 + idx;

    // Batch all 6 loads up front.
    float4 a0 = xb[0];
    float4 a1 = xb[HW4];
    float4 a2 = xb[2 * HW4];
    float4 c0 = xb[256];
    float4 c1 = xb[HW4 + 256];
    float4 c2 = xb[2 * HW4 + 256];

    const float mean_[3] = {0.485f, 0.456f, 0.406f};
    const float istd_[3] = {1.0f / 0.229f, 1.0f / 0.224f, 1.0f / 0.225f};

    #pragma unroll
    for (int i = 0; i < 3; i++) {
        float m0 = sp[i * 3 + 0], m1 = sp[i * 3 + 1], m2 = sp[i * 3 + 2];
        float bi = sp[9 + i];
        float g  = sp[12 + i];
        float is = istd_[i];
        float mo = mean_[i] * is;

        float4 r, q;
        r.x = __powf(fmaf(m0, a0.x, fmaf(m1, a1.x, fmaf(m2, a2.x, bi))), g) * is - mo;
        r.y = __powf(fmaf(m0, a0.y, fmaf(m1, a1.y, fmaf(m2, a2.y, bi))), g) * is - mo;
        r.z = __powf(fmaf(m0, a0.z, fmaf(m1, a1.z, fmaf(m2, a2.z, bi))), g) * is - mo;
        r.w = __powf(fmaf(m0, a0.w, fmaf(m1, a1.w, fmaf(m2, a2.w, bi))), g) * is - mo;
        q.x = __powf(fmaf(m0, c0.x, fmaf(m1, c1.x, fmaf(m2, c2.x, bi))), g) * is - mo;
        q.y = __powf(fmaf(m0, c0.y, fmaf(m1, c1.y, fmaf(m2, c2.y, bi))), g) * is - mo;
        q.z = __powf(fmaf(m0, c0.z, fmaf(m1, c1.z, fmaf(m2, c2.z, bi))), g) * is - mo;
        q.w = __powf(fmaf(m0, c0.w, fmaf(m1, c1.w, fmaf(m2, c2.w, bi))), g) * is - mo;
        __stcs(&ob[(size_t)i * HW4], r);
        __stcs(&ob[(size_t)i * HW4 + 256], q);
    }
}

// ---------------------------------------------------------------------------
extern "C" void kernel_launch(void* const* d_in, const int* in_sizes, int n_in,
                              void* d_out, int out_size) {
    const float* x  = (const float*)d_in[0];
    const float* W1 = (const float*)d_in[1];
    const float* b1 = (const float*)d_in[2];
    const float* W2 = (const float*)d_in[3];
    float* out = (float*)d_out;

    pool_kernel<<<B * C * POOL, 320>>>(x);
    mlp_kernel<<<B, HID>>>(W1, b1, W2);
    transform_kernel<<<dim3(HW4 / 512, B), 256>>>(x, out);
}

// round 4
// speedup vs baseline: 1.0202x; 1.0195x over previous
#include <cuda_runtime.h>

// Shapes (fixed by the problem):
//   x  : (32, 3, 640, 640) fp32
//   W1 : (192, 64), b1 : (64), W2 : (64, 15)
#define B    32
#define C    3
#define H    640
#define W    640
#define HW   (H * W)        // 409600 floats per channel
#define HW4  (HW / 4)       // 102400 float4 per channel
#define POOL 8
#define HID  64
#define NP   15             // 9 (M) + 3 (bias) + 3 (gamma)
#define TGRID (HW4 / 512)   // transform grid.x = 200

// Scratch (allocation-free rule: __device__ globals)
__device__ float g_pooled[B * C * POOL * POOL];   // (b, c*64 + pr*8 + pc)
__device__ float g_params[B * NP];                // per-sample sigmoid outputs

// ---------------------------------------------------------------------------
// Kernel 1: adaptive avg pool 8x8.
// Grid: B*C*POOL = 768 blocks, one per (b, c, pool-row). 320 threads.
// Thread owns float4-column f = tid%160, row-parity r0 = tid/160; streams 40
// rows with a FIXED stride (no div/mod in the loop) so ptxas batches loads.
// Reads ASCENDING through x (samples 0..31): at kernel end, L2 holds the
// TAIL of x, which the (reversed) transform kernel consumes first.
// ---------------------------------------------------------------------------
__global__ __launch_bounds__(320) void pool_kernel(const float* __restrict__ x) {
    int id = blockIdx.x;          // b*24 + c*8 + pr
    int pr = id & 7;
    int bc = id >> 3;             // b*3 + c

    int tid = threadIdx.x;
    int f   = tid % 160;          // float4 column within the row (640/4)
    int r0  = tid / 160;          // 0 or 1

    const float4* base = reinterpret_cast<const float4*>(x)
                       + (size_t)bc * HW4 + (size_t)pr * (80 * 160) + f
                       + (size_t)r0 * 160;

    float acc = 0.0f;
    #pragma unroll
    for (int r = 0; r < 40; r++) {                 // rows r0, r0+2, ..., 78/79
        float4 v = base[(size_t)r * 320];          // stride = 2 rows
        acc += (v.x + v.y) + (v.z + v.w);
    }

    __shared__ float s[320];
    s[tid] = acc;
    __syncthreads();

    if (tid < 8) {                                 // tid == pool column pc
        float t = 0.0f;
        #pragma unroll
        for (int k = 0; k < 20; k++)
            t += s[tid * 20 + k] + s[160 + tid * 20 + k];
        g_pooled[bc * 64 + pr * 8 + tid] = t * (1.0f / 6400.0f);
    }
}

// ---------------------------------------------------------------------------
// Kernel 2: tiny MLP. One block per sample, 64 threads (one per hidden unit).
//   hid = clip(feat @ W1 + b1, 0, 6);  params = sigmoid(hid @ W2)
// ---------------------------------------------------------------------------
__global__ __launch_bounds__(64) void mlp_kernel(const float* __restrict__ W1,
                                                 const float* __restrict__ b1,
                                                 const float* __restrict__ W2) {
    int b = blockIdx.x;
    __shared__ float feat[C * POOL * POOL];  // 192
    __shared__ float hid[HID];

    for (int i = threadIdx.x; i < 192; i += 64)
        feat[i] = g_pooled[b * 192 + i];
    __syncthreads();

    int h = threadIdx.x;
    float s = b1[h];
    #pragma unroll 8
    for (int j = 0; j < 192; j++)
        s = fmaf(feat[j], W1[j * HID + h], s);
    hid[h] = fminf(fmaxf(s, 0.0f), 6.0f);
    __syncthreads();

    if (h < NP) {
        float s2 = 0.0f;
        #pragma unroll 8
        for (int j = 0; j < HID; j++)
            s2 = fmaf(hid[j], W2[j * NP + h], s2);
        g_params[b * NP + h] = 1.0f / (1.0f + __expf(-s2));
    }
}

// ---------------------------------------------------------------------------
// Kernel 3: per-pixel 3x3 color transform + pow(gamma) + normalize.
// REVERSED traversal (LIFO vs pool): sample 31 first, descending addresses
// within each sample, so the first ~120 MB of re-reads hit the x tail that
// pool left resident in L2. Ends at sample 0 -> next graph replay's pool
// starts with L2 hits too. Output stores are streaming (__stcs, evict-first)
// so the 157 MB write stream doesn't evict the resident x lines.
// Grid: (TGRID, B), 256 threads; 2 float4 per plane per thread.
// ---------------------------------------------------------------------------
__global__ __launch_bounds__(256) void transform_kernel(const float* __restrict__ x,
                                                        float* __restrict__ out) {
    int b   = (B - 1) - (int)blockIdx.y;            // samples descending
    int blk = (TGRID - 1) - (int)blockIdx.x;        // addresses descending
    __shared__ float sp[NP];
    if (threadIdx.x < NP) sp[threadIdx.x] = g_params[b * NP + threadIdx.x];
    __syncthreads();

    int idx = blk * 512 + threadIdx.x;              // first float4; second at +256
    const float4* xb = reinterpret_cast<const float4*>(x)   + (size_t)b * 3 * HW4 + idx;
    float4*       ob = reinterpret_cast<float4*>(out)       + (size_t)b * 3 * HW4 + idx;

    // Batch all 6 loads up front.
    float4 a0 = xb[0];
    float4 a1 = xb[HW4];
    float4 a2 = xb[2 * HW4];
    float4 c0 = xb[256];
    float4 c1 = xb[HW4 + 256];
    float4 c2 = xb[2 * HW4 + 256];

    const float mean_[3] = {0.485f, 0.456f, 0.406f};
    const float istd_[3] = {1.0f / 0.229f, 1.0f / 0.224f, 1.0f / 0.225f};

    #pragma unroll
    for (int i = 0; i < 3; i++) {
        float m0 = sp[i * 3 + 0], m1 = sp[i * 3 + 1], m2 = sp[i * 3 + 2];
        float bi = sp[9 + i];
        float g  = sp[12 + i];
        float is = istd_[i];
        float mo = mean_[i] * is;

        float4 r, q;
        r.x = __powf(fmaf(m0, a0.x, fmaf(m1, a1.x, fmaf(m2, a2.x, bi))), g) * is - mo;
        r.y = __powf(fmaf(m0, a0.y, fmaf(m1, a1.y, fmaf(m2, a2.y, bi))), g) * is - mo;
        r.z = __powf(fmaf(m0, a0.z, fmaf(m1, a1.z, fmaf(m2, a2.z, bi))), g) * is - mo;
        r.w = __powf(fmaf(m0, a0.w, fmaf(m1, a1.w, fmaf(m2, a2.w, bi))), g) * is - mo;
        q.x = __powf(fmaf(m0, c0.x, fmaf(m1, c1.x, fmaf(m2, c2.x, bi))), g) * is - mo;
        q.y = __powf(fmaf(m0, c0.y, fmaf(m1, c1.y, fmaf(m2, c2.y, bi))), g) * is - mo;
        q.z = __powf(fmaf(m0, c0.z, fmaf(m1, c1.z, fmaf(m2, c2.z, bi))), g) * is - mo;
        q.w = __powf(fmaf(m0, c0.w, fmaf(m1, c1.w, fmaf(m2, c2.w, bi))), g) * is - mo;
        __stcs(&ob[(size_t)i * HW4], r);
        __stcs(&ob[(size_t)i * HW4 + 256], q);
    }
}

// ---------------------------------------------------------------------------
extern "C" void kernel_launch(void* const* d_in, const int* in_sizes, int n_in,
                              void* d_out, int out_size) {
    const float* x  = (const float*)d_in[0];
    const float* W1 = (const float*)d_in[1];
    const float* b1 = (const float*)d_in[2];
    const float* W2 = (const float*)d_in[3];
    float* out = (float*)d_out;

    pool_kernel<<<B * C * POOL, 320>>>(x);
    mlp_kernel<<<B, HID>>>(W1, b1, W2);
    transform_kernel<<<dim3(TGRID, B), 256>>>(x, out);
}